// round 3
// baseline (speedup 1.0000x reference)
#include <cuda_runtime.h>
#include <math.h>

// Problem constants (fixed shapes from setup_inputs)
#define BI      8
#define SI      4
#define NPARTS  17
#define TAGD    1
#define CCH     ((1 + TAGD) * NPARTS)   // 34
#define HH      128
#define WW      128
#define HW      (HH * WW)               // 16384
#define NPERS   30
#define LTAG    (NPARTS * HW)           // 278528
#define EPSV    1e-6f

// Det term: one (b,p) plane = HW floats = 4096 float4; 256 thr/block -> 16 blocks/plane
#define BLOCKS_PER_PLANE 16
#define DET_BLOCKS  (BI * NPARTS * BLOCKS_PER_PLANE)   // 2176
#define PP_BLOCKS   (BI * SI)                          // 32
#define TOTAL_BLOCKS (DET_BLOCKS + PP_BLOCKS)          // 2208

// Per-block partials + completion counter (no device-side allocation allowed)
__device__ double g_scratch[TOTAL_BLOCKS];
__device__ unsigned int g_done = 0;   // reset to 0 by the last block each call

__global__ void __launch_bounds__(256)
loss_fused_kernel(const float* __restrict__ preds,
                  const float* __restrict__ masks,
                  const float* __restrict__ heatmaps,
                  const int*   __restrict__ kp32,
                  float* __restrict__ out)
{
    const int bid = blockIdx.x;
    const int tid = threadIdx.x;
    const unsigned FULL = 0xffffffffu;

    __shared__ bool s_last;

    if (bid < DET_BLOCKS) {
        // ---------------- det MSE partial ----------------
        const int plane = bid >> 4;                // / BLOCKS_PER_PLANE
        const int chunk = bid & (BLOCKS_PER_PLANE - 1);
        const int b = plane / NPARTS;
        const int p = plane % NPARTS;
        const int hw = (chunk * 256 + tid) * 4;    // float4-aligned element offset

        const float4 m4 = *reinterpret_cast<const float4*>(masks    + (size_t)b * HW + hw);
        const float4 h4 = *reinterpret_cast<const float4*>(heatmaps + ((size_t)b * NPARTS + p) * HW + hw);

        float acc = 0.0f;
#pragma unroll
        for (int s = 0; s < SI; s++) {
            const float4 p4 = *reinterpret_cast<const float4*>(
                preds + (((size_t)(b * SI + s) * CCH + p) * HW + hw));
            const float dx = p4.x - h4.x;
            const float dy = p4.y - h4.y;
            const float dz = p4.z - h4.z;
            const float dw = p4.w - h4.w;
            acc += dx * dx * m4.x + dy * dy * m4.y + dz * dz * m4.z + dw * dw * m4.w;
        }

        // block reduction (8 warps)
#pragma unroll
        for (int o = 16; o > 0; o >>= 1) acc += __shfl_xor_sync(FULL, acc, o);
        __shared__ float wsum[8];
        const int wid = tid >> 5;
        if ((tid & 31) == 0) wsum[wid] = acc;
        __syncthreads();
        if (tid == 0) {
            float s = 0.0f;
#pragma unroll
            for (int w = 0; w < 8; w++) s += wsum[w];
            g_scratch[bid] = (double)s;   // raw sum; tail applies 1/(B*S*17*HW)
        }
    } else {
        // ---------------- pull/push for one (b,s) ----------------
        const int bs = bid - DET_BLOCKS;
        const int b = bs / SI;
        const int s = bs % SI;

        __shared__ float gm[NPERS * NPARTS];   // g * vis
        __shared__ float vf[NPERS * NPARTS];   // vis as float
        __shared__ int   is64_s;

        // Detect keypoint dtype (int64 little-endian with values < 2^31
        // => all odd 32-bit words are zero). Reads stay within the smaller
        // possible buffer (8160 int32 words). Deterministic for fixed inputs.
        if (tid == 0) {
            int orv = 0;
#pragma unroll
            for (int w = 1; w < 64; w += 2) orv |= kp32[w];
            is64_s = (orv == 0) ? 1 : 0;
        }
        __syncthreads();
        const int is64 = is64_s;

        const float* tagbase = preds + ((size_t)(b * SI + s) * CCH + NPARTS) * HW;

        for (int i = tid; i < NPERS * NPARTS; i += blockDim.x) {
            const int p = i / NPARTS;
            const int k = i % NPARTS;
            const int e = (b * NPERS + p) * NPARTS + k;   // entry index
            int idx, visv;
            if (is64) { idx = kp32[4 * e];     visv = kp32[4 * e + 2]; }
            else      { idx = kp32[2 * e];     visv = kp32[2 * e + 1]; }
            const float v = (visv > 0) ? 1.0f : 0.0f;
            // idx is always in [0, LTAG), safe to load unconditionally
            gm[i] = v * tagbase[idx];
            vf[i] = v;
        }
        __syncthreads();

        if (tid < 32) {
            const int p = tid;
            float cnt = 0.0f, sum = 0.0f;
            if (p < NPERS) {
#pragma unroll
                for (int k = 0; k < NPARTS; k++) {
                    cnt += vf[p * NPARTS + k];
                    sum += gm[p * NPARTS + k];
                }
            }
            const float validf = (p < NPERS && cnt > 0.0f) ? 1.0f : 0.0f;
            const float safe   = fmaxf(cnt, 1.0f);
            const float mean   = sum / safe;   // lanes >= NPERS: 0/1 = 0

            float pull_pp = 0.0f;
            if (p < NPERS) {
#pragma unroll
                for (int k = 0; k < NPARTS; k++) {
                    const float d = gm[p * NPARTS + k] - mean * vf[p * NPARTS + k];
                    pull_pp += d * d;
                }
            }
            pull_pp /= safe;   // TAG_DIM == 1

            const unsigned bal = __ballot_sync(FULL, validf > 0.0f);
            const float num = (float)__popc(bal);

            // pull: sum over valid persons / (num + eps)
            float pullv = pull_pp * validf;
#pragma unroll
            for (int o = 16; o > 0; o >>= 1) pullv += __shfl_xor_sync(FULL, pullv, o);
            const float pull_bs = pullv / (num + EPSV);

            // push: row p of exp(-(mean_p - mean_q)^2) over valid q
            float row = 0.0f;
            for (int q = 0; q < NPERS; q++) {
                const float mq = __shfl_sync(FULL, mean,   q);
                const float vq = __shfl_sync(FULL, validf, q);
                const float d  = mean - mq;
                row += vq * expf(-d * d);
            }
            row *= validf;
#pragma unroll
            for (int o = 16; o > 0; o >>= 1) row += __shfl_xor_sync(FULL, row, o);
            const float push_sum = row - num;
            const float push_bs  = push_sum / ((num - 1.0f) * num + EPSV) * 0.5f;

            if (tid == 0) {
                // loss contribution: 0.001*(push+pull) averaged over the B*S cells
                g_scratch[bid] = (double)(0.001f * (push_bs + pull_bs)) / (double)(BI * SI);
            }
        }
    }

    // ---------------- last-block final reduction (fused tail) ----------------
    __threadfence();
    if (tid == 0) {
        const unsigned prev = atomicAdd(&g_done, 1u);
        s_last = (prev == (unsigned)(TOTAL_BLOCKS - 1));
    }
    __syncthreads();

    if (s_last) {
        __threadfence();   // acquire: make all g_scratch writes visible
        const double det_scale = 1.0 / ((double)BI * SI * NPARTS * HW);
        double acc = 0.0;
        // Fixed-order reduction: identical arithmetic regardless of which
        // block executes it -> deterministic output.
        for (int i = tid; i < TOTAL_BLOCKS; i += 256) {
            double v = __ldcg(&g_scratch[i]);
            if (i < DET_BLOCKS) v *= det_scale;   // weight 1.0 * mean over (B,S,17,H,W)
            acc += v;
        }
#pragma unroll
        for (int o = 16; o > 0; o >>= 1) acc += __shfl_xor_sync(FULL, acc, o);
        __shared__ double wsum2[8];
        const int wid = tid >> 5;
        if ((tid & 31) == 0) wsum2[wid] = acc;
        __syncthreads();
        if (tid == 0) {
            double s = 0.0;
#pragma unroll
            for (int w = 0; w < 8; w++) s += wsum2[w];
            out[0] = (float)s;
            g_done = 0;   // reset for next graph replay
        }
    }
}

extern "C" void kernel_launch(void* const* d_in, const int* in_sizes, int n_in,
                              void* d_out, int out_size)
{
    (void)out_size;
    const float* preds    = nullptr;
    const float* masks    = nullptr;
    const float* heatmaps = nullptr;
    const int*   kp       = nullptr;

    // Identify inputs by element count (defensive vs. ordering)
    for (int i = 0; i < n_in; i++) {
        switch (in_sizes[i]) {
            case BI * SI * CCH * HW:   preds    = (const float*)d_in[i]; break;  // 17825792
            case BI * HW:              masks    = (const float*)d_in[i]; break;  // 131072
            case BI * NPARTS * HW:     heatmaps = (const float*)d_in[i]; break;  // 2228224
            case BI * NPERS * NPARTS * 2: kp    = (const int*)d_in[i];   break;  // 8160
            default: break;
        }
    }
    if (!preds    && n_in > 0) preds    = (const float*)d_in[0];
    if (!masks    && n_in > 1) masks    = (const float*)d_in[1];
    if (!heatmaps && n_in > 2) heatmaps = (const float*)d_in[2];
    if (!kp       && n_in > 3) kp       = (const int*)d_in[3];

    loss_fused_kernel<<<TOTAL_BLOCKS, 256>>>(preds, masks, heatmaps, kp, (float*)d_out);
}

// round 4
// speedup vs baseline: 1.1555x; 1.1555x over previous
#include <cuda_runtime.h>
#include <math.h>

// Problem constants (fixed shapes from setup_inputs)
#define BI      8
#define SI      4
#define NPARTS  17
#define TAGD    1
#define CCH     ((1 + TAGD) * NPARTS)   // 34
#define HH      128
#define WW      128
#define HW      (HH * WW)               // 16384
#define NPERS   30
#define LTAG    (NPARTS * HW)           // 278528
#define EPSV    1e-6f

// Det term: one (b,p) plane = HW floats; 8 blocks/plane, each thread does 2 float4
#define BLOCKS_PER_PLANE 8
#define DET_BLOCKS  (BI * NPARTS * BLOCKS_PER_PLANE)   // 1088
#define PP_BLOCKS   (BI * SI)                          // 32
#define TOTAL_BLOCKS (DET_BLOCKS + PP_BLOCKS)          // 1120

// Per-block partials + completion counter (no device-side allocation allowed)
__device__ double g_scratch[TOTAL_BLOCKS];
__device__ unsigned int g_done = 0;   // reset by the last block each call

__global__ void __launch_bounds__(256)
loss_fused_kernel(const float* __restrict__ preds,
                  const float* __restrict__ masks,
                  const float* __restrict__ heatmaps,
                  const int*   __restrict__ kp32,
                  float* __restrict__ out)
{
    const int bid = blockIdx.x;
    const int tid = threadIdx.x;
    const unsigned FULL = 0xffffffffu;

    __shared__ bool s_last;

    if (bid < DET_BLOCKS) {
        // ---------------- det MSE partial ----------------
        const int plane = bid >> 3;                // / BLOCKS_PER_PLANE
        const int chunk = bid & (BLOCKS_PER_PLANE - 1);
        const int b = plane / NPARTS;
        const int p = plane % NPARTS;
        // Each chunk covers 2048 elements; thread handles hw0 and hw0+1024.
        const int hw0 = chunk * 2048 + tid * 4;
        const int hw1 = hw0 + 1024;

        const float* mb = masks    + (size_t)b * HW;
        const float* hb = heatmaps + ((size_t)b * NPARTS + p) * HW;

        const float4 m4a = *reinterpret_cast<const float4*>(mb + hw0);
        const float4 m4b = *reinterpret_cast<const float4*>(mb + hw1);
        const float4 h4a = *reinterpret_cast<const float4*>(hb + hw0);
        const float4 h4b = *reinterpret_cast<const float4*>(hb + hw1);

        float acc = 0.0f;
#pragma unroll
        for (int s = 0; s < SI; s++) {
            const float* pb = preds + ((size_t)(b * SI + s) * CCH + p) * HW;
            const float4 p4a = *reinterpret_cast<const float4*>(pb + hw0);
            const float4 p4b = *reinterpret_cast<const float4*>(pb + hw1);
            {
                const float dx = p4a.x - h4a.x, dy = p4a.y - h4a.y;
                const float dz = p4a.z - h4a.z, dw = p4a.w - h4a.w;
                acc += dx * dx * m4a.x + dy * dy * m4a.y + dz * dz * m4a.z + dw * dw * m4a.w;
            }
            {
                const float dx = p4b.x - h4b.x, dy = p4b.y - h4b.y;
                const float dz = p4b.z - h4b.z, dw = p4b.w - h4b.w;
                acc += dx * dx * m4b.x + dy * dy * m4b.y + dz * dz * m4b.z + dw * dw * m4b.w;
            }
        }

        // block reduction (8 warps)
#pragma unroll
        for (int o = 16; o > 0; o >>= 1) acc += __shfl_xor_sync(FULL, acc, o);
        __shared__ float wsum[8];
        const int wid = tid >> 5;
        if ((tid & 31) == 0) wsum[wid] = acc;
        __syncthreads();
        if (tid == 0) {
            float s = 0.0f;
#pragma unroll
            for (int w = 0; w < 8; w++) s += wsum[w];
            // pre-weighted: weight 1.0 * mean over (B,S,17,H,W)
            g_scratch[bid] = (double)s * (1.0 / ((double)BI * SI * NPARTS * HW));
        }
    } else {
        // ---------------- pull/push for one (b,s) ----------------
        const int bs = bid - DET_BLOCKS;
        const int b = bs / SI;
        const int s = bs % SI;

        __shared__ float gm[NPERS * NPARTS];   // g * vis
        __shared__ float vf[NPERS * NPARTS];   // vis as float
        __shared__ int   is64_s;

        // Detect keypoint dtype (int64 little-endian with values < 2^31
        // => all odd 32-bit words are zero). Reads stay within the smaller
        // possible buffer bound. Deterministic for fixed inputs.
        if (tid == 0) {
            int orv = 0;
#pragma unroll
            for (int w = 1; w < 64; w += 2) orv |= kp32[w];
            is64_s = (orv == 0) ? 1 : 0;
        }
        __syncthreads();
        const int is64 = is64_s;

        const float* tagbase = preds + ((size_t)(b * SI + s) * CCH + NPARTS) * HW;

        for (int i = tid; i < NPERS * NPARTS; i += blockDim.x) {
            const int p = i / NPARTS;
            const int k = i % NPARTS;
            const int e = (b * NPERS + p) * NPARTS + k;   // entry index
            int idx, visv;
            if (is64) { idx = kp32[4 * e];     visv = kp32[4 * e + 2]; }
            else      { idx = kp32[2 * e];     visv = kp32[2 * e + 1]; }
            const float v = (visv > 0) ? 1.0f : 0.0f;
            gm[i] = v * tagbase[idx];   // idx always in [0, LTAG)
            vf[i] = v;
        }
        __syncthreads();

        if (tid < 32) {
            const int p = tid;
            float cnt = 0.0f, sum = 0.0f;
            if (p < NPERS) {
#pragma unroll
                for (int k = 0; k < NPARTS; k++) {
                    cnt += vf[p * NPARTS + k];
                    sum += gm[p * NPARTS + k];
                }
            }
            const float validf = (p < NPERS && cnt > 0.0f) ? 1.0f : 0.0f;
            const float safe   = fmaxf(cnt, 1.0f);
            const float mean   = sum / safe;

            float pull_pp = 0.0f;
            if (p < NPERS) {
#pragma unroll
                for (int k = 0; k < NPARTS; k++) {
                    const float d = gm[p * NPARTS + k] - mean * vf[p * NPARTS + k];
                    pull_pp += d * d;
                }
            }
            pull_pp /= safe;   // TAG_DIM == 1

            const unsigned bal = __ballot_sync(FULL, validf > 0.0f);
            const float num = (float)__popc(bal);

            float pullv = pull_pp * validf;
#pragma unroll
            for (int o = 16; o > 0; o >>= 1) pullv += __shfl_xor_sync(FULL, pullv, o);
            const float pull_bs = pullv / (num + EPSV);

            float row = 0.0f;
            for (int q = 0; q < NPERS; q++) {
                const float mq = __shfl_sync(FULL, mean,   q);
                const float vq = __shfl_sync(FULL, validf, q);
                const float d  = mean - mq;
                row += vq * expf(-d * d);
            }
            row *= validf;
#pragma unroll
            for (int o = 16; o > 0; o >>= 1) row += __shfl_xor_sync(FULL, row, o);
            const float push_sum = row - num;
            const float push_bs  = push_sum / ((num - 1.0f) * num + EPSV) * 0.5f;

            if (tid == 0) {
                g_scratch[bid] = (double)(0.001f * (push_bs + pull_bs)) / (double)(BI * SI);
            }
        }
        __syncthreads();
    }

    // ------------- fenceless completion protocol (no CCTL.IVALL) -------------
    // tid0's scratch store is drained by the RELEASE atomic below; the last
    // block's tail loads are control-dependent on the returned count (in-order
    // issue => no load starts before the acquire completes) and use __ldcg.
    if (tid == 0) {
        unsigned prev;
        asm volatile("atom.acq_rel.gpu.global.add.u32 %0, [%1], 1;"
                     : "=r"(prev) : "l"(&g_done) : "memory");
        s_last = (prev == (unsigned)(TOTAL_BLOCKS - 1));
    }
    __syncthreads();

    if (s_last) {
        double acc = 0.0;
        // Fixed-order reduction -> deterministic regardless of which block runs it.
        for (int i = tid; i < TOTAL_BLOCKS; i += 256) {
            acc += __ldcg(&g_scratch[i]);
        }
#pragma unroll
        for (int o = 16; o > 0; o >>= 1) acc += __shfl_xor_sync(FULL, acc, o);
        __shared__ double wsum2[8];
        const int wid = tid >> 5;
        if ((tid & 31) == 0) wsum2[wid] = acc;
        __syncthreads();
        if (tid == 0) {
            double s = 0.0;
#pragma unroll
            for (int w = 0; w < 8; w++) s += wsum2[w];
            out[0] = (float)s;
            g_done = 0;   // all blocks arrived; safe plain store, visible next launch
        }
    }
}

extern "C" void kernel_launch(void* const* d_in, const int* in_sizes, int n_in,
                              void* d_out, int out_size)
{
    (void)out_size;
    const float* preds    = nullptr;
    const float* masks    = nullptr;
    const float* heatmaps = nullptr;
    const int*   kp       = nullptr;

    // Identify inputs by element count (defensive vs. ordering)
    for (int i = 0; i < n_in; i++) {
        switch (in_sizes[i]) {
            case BI * SI * CCH * HW:   preds    = (const float*)d_in[i]; break;  // 17825792
            case BI * HW:              masks    = (const float*)d_in[i]; break;  // 131072
            case BI * NPARTS * HW:     heatmaps = (const float*)d_in[i]; break;  // 2228224
            case BI * NPERS * NPARTS * 2: kp    = (const int*)d_in[i];   break;  // 8160
            default: break;
        }
    }
    if (!preds    && n_in > 0) preds    = (const float*)d_in[0];
    if (!masks    && n_in > 1) masks    = (const float*)d_in[1];
    if (!heatmaps && n_in > 2) heatmaps = (const float*)d_in[2];
    if (!kp       && n_in > 3) kp       = (const int*)d_in[3];

    loss_fused_kernel<<<TOTAL_BLOCKS, 256>>>(preds, masks, heatmaps, kp, (float*)d_out);
}